// round 3
// baseline (speedup 1.0000x reference)
#include <cuda_runtime.h>
#include <cstdint>
#include <cstddef>

// ---------------- problem constants ----------------
#define D_MODEL   1024
#define D_PROJ    256
#define MTILE     64                   // rows per CTA
#define KCHUNK    16                   // fp32 per K chunk = 64B per row
#define NCHUNKS   (D_MODEL / KCHUNK)   // 64
#define EPS1      1e-5f

// smem map (bytes):
//   [0, 4096)      suv: u[256] v[256] g2[256] b2[256]
//   [4096, 4608)   s1p[64], s2p[64]
//   [4608, 5120)   ca[64], cb[64]
//   [8192, ...)    4 pipeline stages: A 4KB + B 16KB each
//   epilogue reuses stage0: rowacc[64][4][2], mu2[64], rs2[64]
#define SMEM_STAGE_OFF 8192
#define A_BYTES   (MTILE * KCHUNK * 4)     // 4096
#define B_BYTES   (D_PROJ * KCHUNK * 4)    // 16384
#define STAGE_BYTES (A_BYTES + B_BYTES)    // 20480
#define SMEM_BYTES (SMEM_STAGE_OFF + 4 * STAGE_BYTES)   // 90112

// ---------------- device scratch ----------------
// g_Wp layout: [p][kc*16 + s], slot s = 4*(kk&3) + (kk>>2) holds k_local kk
// (so the 16B group q contains k = q, q+4, q+8, q+12 -> feeds 2 mma k-steps).
__device__ float g_Wp[D_PROJ * D_MODEL];
__device__ float g_u[D_PROJ];
__device__ float g_v[D_PROJ];

// ---------------- helpers ----------------
static __device__ __forceinline__ uint32_t smem_u32(const void* p) {
    uint32_t a;
    asm("{ .reg .u64 t; cvta.to.shared.u64 t, %1; cvt.u32.u64 %0, t; }" : "=r"(a) : "l"(p));
    return a;
}

static __device__ __forceinline__ uint32_t swz(int r) {   // 16B-group xor swizzle
    return (uint32_t)((r + (r >> 2)) & 3);
}

#define CP_COMMIT() asm volatile("cp.async.commit_group;" ::: "memory")

static __device__ __forceinline__ uint32_t f2tf32(float f) {
    uint32_t u;
    asm("cvt.rna.tf32.f32 %0, %1;" : "=r"(u) : "f"(f));
    return u;
}

#define MMA_TF32(d, a0, a1, a2, a3, b0, b1)                                   \
    asm volatile("mma.sync.aligned.m16n8k8.row.col.f32.tf32.tf32.f32 "        \
        "{%0,%1,%2,%3}, {%4,%5,%6,%7}, {%8,%9}, {%0,%1,%2,%3};"               \
        : "+f"((d)[0]), "+f"((d)[1]), "+f"((d)[2]), "+f"((d)[3])              \
        : "r"(a0), "r"(a1), "r"(a2), "r"(a3), "r"(b0), "r"(b1))

#define LDS128F(v, addr)                                                      \
    asm volatile("ld.shared.v4.f32 {%0,%1,%2,%3}, [%4];"                      \
        : "=f"((v).x), "=f"((v).y), "=f"((v).z), "=f"((v).w) : "r"(addr))

#define LDS64U(r0, r1, addr)                                                  \
    asm volatile("ld.shared.v2.b32 {%0,%1}, [%2];"                            \
        : "=r"(r0), "=r"(r1) : "r"(addr))

// ---------------- prep: W' = g1.*W (tf32-rna), permuted layout; u, v ----------------
__global__ void __launch_bounds__(256) prep_kernel(
    const float* __restrict__ W, const float* __restrict__ g1,
    const float* __restrict__ b1, const float* __restrict__ bias)
{
    __shared__ float ru[8], rv[8];
    int p = blockIdx.x, t = threadIdx.x;
    const float* wrow = W + (size_t)p * D_MODEL;
    float u = 0.f, v = 0.f;
#pragma unroll
    for (int i = 0; i < 4; ++i) {
        int d = t + i * 256;
        float w  = wrow[d];
        float gw = g1[d] * w;
        u += gw;
        v += b1[d] * w;
        int kc = d >> 4, kk = d & 15;
        int s = ((kk & 3) << 2) | (kk >> 2);
        g_Wp[(size_t)p * D_MODEL + kc * 16 + s] = __uint_as_float(f2tf32(gw));
    }
#pragma unroll
    for (int o = 16; o > 0; o >>= 1) {
        u += __shfl_xor_sync(0xFFFFFFFFu, u, o);
        v += __shfl_xor_sync(0xFFFFFFFFu, v, o);
    }
    if ((t & 31) == 0) { ru[t >> 5] = u; rv[t >> 5] = v; }
    __syncthreads();
    if (t == 0) {
        float uu = 0.f, vv = 0.f;
#pragma unroll
        for (int i = 0; i < 8; ++i) { uu += ru[i]; vv += rv[i]; }
        g_u[p] = uu;
        g_v[p] = vv + bias[p];
    }
}

// ---------------- chunk loader ----------------
__device__ __forceinline__ void load_chunk(uint32_t sb, const char* xb, const char* wb,
                                           int tid, int kc, int stg)
{
    uint32_t abase = sb + SMEM_STAGE_OFF + (uint32_t)stg * STAGE_BYTES;
    uint32_t bbase = abase + A_BYTES;
    // A: 1024 floats. thread -> row r = tid>>2, slot-byte jj = tid&3, m = 0..3.
    // kk = 4*jj + m  (c = m, j = jj)  -> phys group m ^ swz(r), byte jj*4.
    {
        int r  = tid >> 2;
        int jj = tid & 3;
        const char* src = xb + (size_t)kc * 64 + (size_t)r * 4096 + (size_t)jj * 16;
        uint32_t dstrow = abase + (uint32_t)r * 64 + (uint32_t)jj * 4;
        uint32_t sw = swz(r);
#pragma unroll
        for (int m = 0; m < 4; ++m) {
            asm volatile("cp.async.ca.shared.global [%0], [%1], 4;"
                         :: "r"(dstrow + (((uint32_t)m ^ sw) << 4)), "l"(src + m * 4));
        }
    }
    // B: 4096 floats via 16B cp.async (g_Wp already tf32+slot-permuted)
    {
        int q = tid & 3;
#pragma unroll
        for (int i = 0; i < 4; ++i) {
            int p = i * 64 + (tid >> 2);
            const char* src = wb + (size_t)p * 4096 + (size_t)kc * 64 + (size_t)q * 16;
            uint32_t dst = bbase + (uint32_t)p * 64 + ((((uint32_t)q) ^ swz(p)) << 4);
            asm volatile("cp.async.cg.shared.global [%0], [%1], 16;"
                         :: "r"(dst), "l"(src));
        }
    }
}

// ---------------- main fused kernel ----------------
__global__ void __launch_bounds__(256, 2) fused_kernel(
    const float* __restrict__ x,
    const float* __restrict__ g2v, const float* __restrict__ b2v,
    float* __restrict__ out)
{
    extern __shared__ char smem[];
    const uint32_t sb = smem_u32(smem);
    const int tid  = threadIdx.x;
    const int lane = tid & 31;
    const int wid  = tid >> 5;
    const int wm   = wid >> 2;          // 0..1
    const int wn   = wid & 3;           // 0..3
    const int qt   = lane & 3;
    const int qr   = lane >> 2;

    float* suv = (float*)smem;          // u, v, g2, b2
    suv[tid]       = g_u[tid];
    suv[256 + tid] = g_v[tid];
    suv[512 + tid] = g2v[tid];
    suv[768 + tid] = b2v[tid];

    const size_t row0 = (size_t)blockIdx.x * MTILE;
    const char* xb = (const char*)(x + row0 * D_MODEL);
    const char* wb = (const char*)g_Wp;

    float acc[2][8][4];
#pragma unroll
    for (int a = 0; a < 2; ++a)
#pragma unroll
        for (int b = 0; b < 8; ++b)
#pragma unroll
            for (int c = 0; c < 4; ++c) acc[a][b][c] = 0.f;

    // LN1 partials in registers (only wn==0 warps accumulate; rows
    // wm*32 + mt*16 + qr (+8), full k covered by the 4 qt lanes).
    float s1r[4] = {0.f, 0.f, 0.f, 0.f};
    float s2r[4] = {0.f, 0.f, 0.f, 0.f};

    load_chunk(sb, xb, wb, tid, 0, 0); CP_COMMIT();
    load_chunk(sb, xb, wb, tid, 1, 1); CP_COMMIT();
    load_chunk(sb, xb, wb, tid, 2, 2); CP_COMMIT();

#pragma unroll 1
    for (int kc = 0; kc < NCHUNKS; ++kc) {
        const int stg = kc & 3;
        asm volatile("cp.async.wait_group 2;" ::: "memory");
        __syncthreads();
        if (kc + 3 < NCHUNKS) load_chunk(sb, xb, wb, tid, kc + 3, (kc + 3) & 3);
        CP_COMMIT();

        const uint32_t abase = sb + SMEM_STAGE_OFF + (uint32_t)stg * STAGE_BYTES;
        const uint32_t bbase = abase + A_BYTES;

        // ---- A fragments (+ LN1 stats from pre-cvt floats) ----
        uint32_t au[2][8];
#pragma unroll
        for (int mt = 0; mt < 2; ++mt) {
            int r0 = wm * 32 + mt * 16 + qr;
            int r8 = r0 + 8;
            float4 alo, ahi;
            LDS128F(alo, abase + (uint32_t)r0 * 64 + ((((uint32_t)qt) ^ swz(r0)) << 4));
            LDS128F(ahi, abase + (uint32_t)r8 * 64 + ((((uint32_t)qt) ^ swz(r8)) << 4));
            if (wn == 0) {
                s1r[mt * 2]     += (alo.x + alo.y) + (alo.z + alo.w);
                s2r[mt * 2]     += (alo.x * alo.x + alo.y * alo.y)
                                 + (alo.z * alo.z + alo.w * alo.w);
                s1r[mt * 2 + 1] += (ahi.x + ahi.y) + (ahi.z + ahi.w);
                s2r[mt * 2 + 1] += (ahi.x * ahi.x + ahi.y * ahi.y)
                                 + (ahi.z * ahi.z + ahi.w * ahi.w);
            }
            au[mt][0] = f2tf32(alo.x); au[mt][1] = f2tf32(ahi.x);
            au[mt][2] = f2tf32(alo.y); au[mt][3] = f2tf32(ahi.y);
            au[mt][4] = f2tf32(alo.z); au[mt][5] = f2tf32(ahi.z);
            au[mt][6] = f2tf32(alo.w); au[mt][7] = f2tf32(ahi.w);
        }

        // ---- two k-steps of m16n8k8 ----
#pragma unroll
        for (int s = 0; s < 2; ++s) {
            uint32_t b0[8], b1[8];
#pragma unroll
            for (int nt = 0; nt < 8; ++nt) {
                int p = wn * 64 + nt * 8 + qr;
                uint32_t addr = bbase + (uint32_t)p * 64
                              + ((((uint32_t)qt) ^ swz(p)) << 4) + (uint32_t)s * 8;
                LDS64U(b0[nt], b1[nt], addr);
            }
#pragma unroll
            for (int mt = 0; mt < 2; ++mt)
#pragma unroll
                for (int nt = 0; nt < 8; ++nt)
                    MMA_TF32(acc[mt][nt], au[mt][4 * s], au[mt][4 * s + 1],
                             au[mt][4 * s + 2], au[mt][4 * s + 3], b0[nt], b1[nt]);
        }
    }

    // ---------------- LN1 finalize ----------------
    float* s1p = (float*)(smem + 4096);         // [64]
    float* s2p = s1p + 64;                      // [64]
    float* ca  = (float*)(smem + 4608);         // [64]
    float* cb  = ca + 64;                       // [64]
    float* rowacc = (float*)(smem + SMEM_STAGE_OFF);        // [64][4][2]
    float* mu2a = rowacc + 512;                 // [64]
    float* rs2a = mu2a + 64;                    // [64]

    __syncthreads();                            // mainloop fully done
    if (wn == 0) {
#pragma unroll
        for (int sl = 0; sl < 4; ++sl) {
            float a = s1r[sl], b = s2r[sl];
            a += __shfl_xor_sync(0xFFFFFFFFu, a, 1);
            b += __shfl_xor_sync(0xFFFFFFFFu, b, 1);
            a += __shfl_xor_sync(0xFFFFFFFFu, a, 2);
            b += __shfl_xor_sync(0xFFFFFFFFu, b, 2);
            if (qt == 0) {
                int rr = wm * 32 + (sl >> 1) * 16 + qr + 8 * (sl & 1);
                s1p[rr] = a;
                s2p[rr] = b;
            }
        }
    }
    rowacc[tid] = 0.f; rowacc[tid + 256] = 0.f;
    __syncthreads();

    if (tid < 64) {
        float mu  = s1p[tid] * (1.0f / (float)D_MODEL);
        float var = fmaf(-mu, mu, s2p[tid] * (1.0f / (float)D_MODEL));
        float rs  = rsqrtf(var + EPS1);
        ca[tid] = rs;
        cb[tid] = -mu * rs;
    }
    __syncthreads();

    // ---------------- h = ca*acc + cb*u + v; LN2 partial sums ----------------
#pragma unroll
    for (int mt = 0; mt < 2; ++mt) {
#pragma unroll
        for (int b = 0; b < 2; ++b) {
            int rr = wm * 32 + mt * 16 + qr + 8 * b;
            float cav = ca[rr], cbv = cb[rr];
            float t1 = 0.f, t2 = 0.f;
#pragma unroll
            for (int nt = 0; nt < 8; ++nt) {
                int p0 = wn * 64 + nt * 8 + 2 * qt;
                float h0 = fmaf(cav, acc[mt][nt][2 * b],     fmaf(cbv, suv[p0],     suv[256 + p0]));
                float h1 = fmaf(cav, acc[mt][nt][2 * b + 1], fmaf(cbv, suv[p0 + 1], suv[256 + p0 + 1]));
                acc[mt][nt][2 * b]     = h0;
                acc[mt][nt][2 * b + 1] = h1;
                t1 += h0 + h1;
                t2 += h0 * h0 + h1 * h1;
            }
            t1 += __shfl_xor_sync(0xFFFFFFFFu, t1, 1);
            t2 += __shfl_xor_sync(0xFFFFFFFFu, t2, 1);
            t1 += __shfl_xor_sync(0xFFFFFFFFu, t1, 2);
            t2 += __shfl_xor_sync(0xFFFFFFFFu, t2, 2);
            if (qt == 0) {
                rowacc[(rr * 4 + wn) * 2]     = t1;
                rowacc[(rr * 4 + wn) * 2 + 1] = t2;
            }
        }
    }
    __syncthreads();

    if (tid < 64) {
        float t1 = 0.f, t2 = 0.f;
#pragma unroll
        for (int w = 0; w < 4; ++w) {
            t1 += rowacc[(tid * 4 + w) * 2];
            t2 += rowacc[(tid * 4 + w) * 2 + 1];
        }
        float mu  = t1 * (1.0f / (float)D_PROJ);
        float var = fmaf(-mu, mu, t2 * (1.0f / (float)D_PROJ));
        mu2a[tid] = mu;
        rs2a[tid] = rsqrtf(var + EPS1);
    }
    __syncthreads();

    // ---------------- normalize + store ----------------
    float* outp = out + row0 * D_PROJ;
#pragma unroll
    for (int mt = 0; mt < 2; ++mt) {
#pragma unroll
        for (int b = 0; b < 2; ++b) {
            int rr = wm * 32 + mt * 16 + qr + 8 * b;
            float mu = mu2a[rr], rs = rs2a[rr];
#pragma unroll
            for (int nt = 0; nt < 8; ++nt) {
                int p0 = wn * 64 + nt * 8 + 2 * qt;
                float o0 = fmaf((acc[mt][nt][2 * b]     - mu) * rs, suv[512 + p0],     suv[768 + p0]);
                float o1 = fmaf((acc[mt][nt][2 * b + 1] - mu) * rs, suv[512 + p0 + 1], suv[768 + p0 + 1]);
                float2 o = make_float2(o0, o1);
                *(float2*)(outp + (size_t)rr * D_PROJ + p0) = o;
            }
        }
    }
}

// ---------------- launch ----------------
extern "C" void kernel_launch(void* const* d_in, const int* in_sizes, int n_in,
                              void* d_out, int out_size)
{
    const float* x    = (const float*)d_in[0];
    const float* g1   = (const float*)d_in[1];
    const float* b1   = (const float*)d_in[2];
    const float* W    = (const float*)d_in[3];
    const float* bias = (const float*)d_in[4];
    const float* g2   = (const float*)d_in[5];
    const float* b2   = (const float*)d_in[6];
    float* out = (float*)d_out;

    int n_tok = in_sizes[0] / D_MODEL;          // 65536
    int grid  = n_tok / MTILE;                  // 1024

    prep_kernel<<<D_PROJ, 256>>>(W, g1, b1, bias);

    cudaFuncSetAttribute(fused_kernel, cudaFuncAttributeMaxDynamicSharedMemorySize, SMEM_BYTES);
    fused_kernel<<<grid, 256, SMEM_BYTES>>>(x, g2, b2, out);
}